// round 14
// baseline (speedup 1.0000x reference)
#include <cuda_runtime.h>

#define GS      20
#define PARAM   40
#define NN      (GS * PARAM)     // 800
#define NSYS    80               // B*A
#define MST     44               // padded matrix stride
#define NITER   2                // sweeps (measured: trunc_3 ~ 8e-8 -> trunc_2 ~ 3e-6, bias 1.5e-5 dominates)

// ---------------------------------------------------------------------------
// One CTA per system, 800 threads.
// P = I(x)S + M(x)Ng,  F = S/2 - I.  Bpre = 0.5(I-F)(I+F^2+F^4): BS = I-F^6
// (bias 1.5e-5, measured).  x = b - (M(x)C)x,  C=Bpre*Ng, b=(I(x)Bpre)v.
// 2 Richardson sweeps.  Prep GEMMs: 20-warp cooperative tiling (5 warps/SMSP).
// ---------------------------------------------------------------------------

#define GM_PLAIN 0   // D = A*Bm
#define GM_H     1   // D = A*Bm + A + I      (H = G^2 + G + I, A=B=G)
#define GM_BF    2   // D = 0.5*(Bm - A*Bm)   (B = 0.5*(H - F*H))

// Warp-cooperative 40x40 GEMM, 20 warps (t < 640).
// Warp w: rows {2w, 2w+1}. lane: rr=lane>>4 -> row 2w+rr, cc=lane&15.
// Cols per thread: {2cc, 2cc+1}; cc<4 additionally {32+2cc, 33+2cc}.
// B k-row read c0: 16 distinct float2 = 128B contiguous -> 1 conflict-free wf
// (rr halves broadcast-dup). A: 2 distinct float4/warp -> broadcast.
template <int MODE>
__device__ __forceinline__ void gemm40w(float* __restrict__ D,
                                        const float* __restrict__ A,
                                        const float* __restrict__ B,
                                        int t)
{
    if (t >= 640) return;
    const int lane = t & 31;
    const int rr   = lane >> 4;          // 0..1
    const int cc   = lane & 15;          // 0..15
    const int r    = 2 * (t >> 5) + rr;  // 0..39
    const int c0   = 2 * cc;             // 0..30
    const int c1   = 32 + 2 * cc;        // 32..38 (cc<4 only)
    const bool has1 = (cc < 4);

    float a00 = 0.f, a01 = 0.f, a10 = 0.f, a11 = 0.f;
    const float4* Arow = (const float4*)(A + r * MST);
    #pragma unroll
    for (int k4 = 0; k4 < 10; ++k4) {
        float4 a4 = Arow[k4];
        #pragma unroll
        for (int j = 0; j < 4; ++j) {
            float av = (j == 0) ? a4.x : (j == 1) ? a4.y : (j == 2) ? a4.z : a4.w;
            const float* Bk = B + (4 * k4 + j) * MST;
            float2 b0 = *(const float2*)(Bk + c0);
            a00 = fmaf(av, b0.x, a00);  a01 = fmaf(av, b0.y, a01);
            if (has1) {
                float2 b1 = *(const float2*)(Bk + c1);
                a10 = fmaf(av, b1.x, a10);  a11 = fmaf(av, b1.y, a11);
            }
        }
    }

    #pragma unroll
    for (int s = 0; s < 2; ++s) {
        if (s == 1 && !has1) break;
        int   c  = (s == 0) ? c0 : c1;
        float v0 = (s == 0) ? a00 : a10;
        float v1 = (s == 0) ? a01 : a11;
        float2 o;
        if (MODE == GM_H) {
            o.x = v0 + A[r * MST + c]     + (r == c     ? 1.0f : 0.0f);
            o.y = v1 + A[r * MST + c + 1] + (r == c + 1 ? 1.0f : 0.0f);
        } else if (MODE == GM_BF) {
            o.x = 0.5f * (B[r * MST + c]     - v0);
            o.y = 0.5f * (B[r * MST + c + 1] - v1);
        } else {
            o.x = v0; o.y = v1;
        }
        *(float2*)(D + r * MST + c) = o;
    }
}

// dot(Mat[p,:], vec[g,:]) with float4 reads
__device__ __forceinline__ float rowdot40(const float* __restrict__ Mrow,
                                          const float* __restrict__ vrow)
{
    const float4* m4 = (const float4*)Mrow;
    const float4* v4 = (const float4*)vrow;
    float acc = 0.f;
    #pragma unroll
    for (int i = 0; i < 10; ++i) {
        float4 m = m4[i], v = v4[i];
        acc = fmaf(m.x, v.x, acc);
        acc = fmaf(m.y, v.y, acc);
        acc = fmaf(m.z, v.z, acc);
        acc = fmaf(m.w, v.w, acc);
    }
    return acc;
}

__global__ __launch_bounds__(NN, 1)
void gliam_fused_kernel(const float* __restrict__ mat,        // (80,20,20)
                        const float* __restrict__ val,        // (80,800)
                        const float* __restrict__ selfintact, // (40,40)
                        const float* __restrict__ neigintact, // (40,40)
                        float* __restrict__ out)              // (80,800)
{
    __shared__ __align__(16) float mF [PARAM * MST];  // F = S/2 - I
    __shared__ __align__(16) float mG [PARAM * MST];  // G = F^2
    __shared__ __align__(16) float mH [PARAM * MST];  // H = I + G + G^2
    __shared__ __align__(16) float mB [PARAM * MST];  // Bpre
    __shared__ __align__(16) float mNg[PARAM * MST];  // Ng
    __shared__ __align__(16) float mC [PARAM * MST];  // C = Bpre*Ng
    __shared__ __align__(16) float sx [NN];           // iterate
    __shared__ __align__(16) float sT [NN];           // T scratch
    __shared__ __align__(16) float sV [NN];           // v
    __shared__ __align__(16) float sM [GS * GS];      // M

    const int sys = blockIdx.x;
    const int t   = threadIdx.x;     // 0..799
    const int g   = t / PARAM;       // 0..19
    const int p   = t % PARAM;       // 0..39

    // ---- stage inputs ----
    {
        int i0 = t, i1 = t + NN;
        int r0 = i0 / PARAM, c0 = i0 % PARAM;
        int r1 = i1 / PARAM, c1 = i1 % PARAM;
        mF [r0 * MST + c0] = 0.5f * selfintact[i0] - (r0 == c0 ? 1.0f : 0.0f);
        mF [r1 * MST + c1] = 0.5f * selfintact[i1] - (r1 == c1 ? 1.0f : 0.0f);
        mNg[r0 * MST + c0] = neigintact[i0];
        mNg[r1 * MST + c1] = neigintact[i1];
        sV[t] = val[sys * NN + t];
        if (t < GS * GS) sM[t] = mat[sys * GS * GS + t];
    }
    __syncthreads();

    // ---- prep: 4 warp-cooperative GEMMs (20 warps each) ----
    gemm40w<GM_PLAIN>(mG, mF, mF, t);   __syncthreads();  // G = F^2
    gemm40w<GM_H    >(mH, mG, mG, t);   __syncthreads();  // H = I + G + G^2
    gemm40w<GM_BF   >(mB, mF, mH, t);   __syncthreads();  // Bpre = 0.5(H - F*H)
    gemm40w<GM_PLAIN>(mC, mB, mNg, t);                    // C = Bpre*Ng
    // b = (I(x)Bpre) v for this element (mB ready above; all 800 threads).
    float b = rowdot40(&mB[p * MST], &sV[g * PARAM]);
    sx[t] = b;                        // x0 = b (sx untouched so far, no pre-barrier)
    __syncthreads();                  // mC stores + sx visible

    // ---- C[p,:] into registers ----
    float4 creg[10];
    #pragma unroll
    for (int i = 0; i < 10; ++i)
        creg[i] = *(const float4*)&mC[p * MST + 4 * i];

    const float*  Mrow = &sM[g * GS];
    const float4* xrow = (const float4*)&sx[g * PARAM];

    // ---- Richardson sweeps: x <- b - (M (x) C) x  (2 barriers/sweep) ----
    #pragma unroll 1
    for (int it = 0; it < NITER; ++it) {
        // Phase A: T[g,p] = sum_q C[p,q] x[g,q]
        float tv = 0.f;
        #pragma unroll
        for (int i = 0; i < 10; ++i) {
            float4 c  = creg[i];
            float4 x4 = xrow[i];        // broadcast within g-group
            tv = fmaf(c.x, x4.x, tv);
            tv = fmaf(c.y, x4.y, tv);
            tv = fmaf(c.z, x4.z, tv);
            tv = fmaf(c.w, x4.w, tv);
        }
        sT[t] = tv;
        __syncthreads();                // all phase-A sx reads + sT writes done

        // Phase B: x[g,p] = b - sum_g2 M[g,g2] T[g2,p]
        float acc = b;
        #pragma unroll
        for (int g2 = 0; g2 < GS; ++g2)
            acc = fmaf(-Mrow[g2], sT[g2 * PARAM + p], acc);  // M bcast, T conflict-free

        if (it == NITER - 1) {
            acc = fminf(fmaxf(acc, -1.0f), 1.0f);   // advrelu == clip
            out[sys * NN + t] = acc;
        } else {
            // safe: all phase-A sx reads completed before the barrier above
            sx[t] = acc;
            __syncthreads();
        }
    }
}

extern "C" void kernel_launch(void* const* d_in, const int* in_sizes, int n_in,
                              void* d_out, int out_size)
{
    const float* mat        = (const float*)d_in[0];
    const float* val        = (const float*)d_in[1];
    const float* selfintact = (const float*)d_in[2];
    const float* neigintact = (const float*)d_in[3];
    float* out = (float*)d_out;

    gliam_fused_kernel<<<NSYS, NN>>>(mat, val, selfintact, neigintact, out);
}

// round 15
// speedup vs baseline: 1.1382x; 1.1382x over previous
#include <cuda_runtime.h>

#define GS      20
#define PARAM   40
#define NN      (GS * PARAM)     // 800
#define NSYS    80               // B*A
#define MST     44               // padded matrix stride
#define NITER   2                // sweeps (R14 measured: rel_err 4.7e-5, 21x under gate)

// ---------------------------------------------------------------------------
// One CTA per system, 800 threads.
// P = I(x)S + M(x)Ng,  F = S/2 - I.  Bpre = 0.5(I-F)(I+F^2+F^4): BS = I-F^6
// (bias 1.5e-5 measured).  x = b - (M(x)C)x,  C=Bpre*Ng, b=(I(x)Bpre)v.
// 2 Richardson sweeps.  Prep GEMMs: 10-warp cooperative tiling (R13, proven:
// B-operand dedup across row-lanes keeps crossbar traffic at 64KB/GEMM).
// ---------------------------------------------------------------------------

#define GM_PLAIN 0   // D = A*Bm
#define GM_H     1   // D = A*Bm + A + I      (H = G^2 + G + I, A=B=G)
#define GM_BF    2   // D = 0.5*(Bm - A*Bm)   (B = 0.5*(H - F*H))

// Warp-cooperative 40x40 GEMM, 10 warps (t < 320).
// Warp w: rows 4w..4w+3.  lane -> rr = lane>>3 (row), cc = lane&7.
// Cols per thread: {2cc,2cc+1}, {2cc+16,2cc+17}, and {2cc+32,2cc+33} if cc<4.
template <int MODE>
__device__ __forceinline__ void gemm40w(float* __restrict__ D,
                                        const float* __restrict__ A,
                                        const float* __restrict__ B,
                                        int t)
{
    if (t >= 320) return;
    const int lane = t & 31;
    const int rr   = lane >> 3;          // 0..3
    const int cc   = lane & 7;           // 0..7
    const int r    = 4 * (t >> 5) + rr;  // 0..39
    const int c0   = 2 * cc;             // 0..15
    const int c1   = c0 + 16;            // 16..31
    const int c2   = c0 + 32;            // 32..39 (cc<4 only)
    const bool has2 = (cc < 4);

    float a00 = 0.f, a01 = 0.f, a10 = 0.f, a11 = 0.f, a20 = 0.f, a21 = 0.f;
    const float4* Arow = (const float4*)(A + r * MST);
    #pragma unroll
    for (int k4 = 0; k4 < 10; ++k4) {
        float4 a4 = Arow[k4];
        #pragma unroll
        for (int j = 0; j < 4; ++j) {
            float av = (j == 0) ? a4.x : (j == 1) ? a4.y : (j == 2) ? a4.z : a4.w;
            const float* Bk = B + (4 * k4 + j) * MST;
            float2 b0 = *(const float2*)(Bk + c0);
            float2 b1 = *(const float2*)(Bk + c1);
            a00 = fmaf(av, b0.x, a00);  a01 = fmaf(av, b0.y, a01);
            a10 = fmaf(av, b1.x, a10);  a11 = fmaf(av, b1.y, a11);
            if (has2) {
                float2 b2 = *(const float2*)(Bk + c2);
                a20 = fmaf(av, b2.x, a20);  a21 = fmaf(av, b2.y, a21);
            }
        }
    }

    #pragma unroll
    for (int s = 0; s < 3; ++s) {
        if (s == 2 && !has2) break;
        int  c  = (s == 0) ? c0 : (s == 1) ? c1 : c2;
        float v0 = (s == 0) ? a00 : (s == 1) ? a10 : a20;
        float v1 = (s == 0) ? a01 : (s == 1) ? a11 : a21;
        float2 o;
        if (MODE == GM_H) {
            o.x = v0 + A[r * MST + c]     + (r == c     ? 1.0f : 0.0f);
            o.y = v1 + A[r * MST + c + 1] + (r == c + 1 ? 1.0f : 0.0f);
        } else if (MODE == GM_BF) {
            o.x = 0.5f * (B[r * MST + c]     - v0);
            o.y = 0.5f * (B[r * MST + c + 1] - v1);
        } else {
            o.x = v0; o.y = v1;
        }
        *(float2*)(D + r * MST + c) = o;
    }
}

// dot(Mat[p,:], vec[g,:]) with float4 reads
__device__ __forceinline__ float rowdot40(const float* __restrict__ Mrow,
                                          const float* __restrict__ vrow)
{
    const float4* m4 = (const float4*)Mrow;
    const float4* v4 = (const float4*)vrow;
    float acc = 0.f;
    #pragma unroll
    for (int i = 0; i < 10; ++i) {
        float4 m = m4[i], v = v4[i];
        acc = fmaf(m.x, v.x, acc);
        acc = fmaf(m.y, v.y, acc);
        acc = fmaf(m.z, v.z, acc);
        acc = fmaf(m.w, v.w, acc);
    }
    return acc;
}

__global__ __launch_bounds__(NN, 1)
void gliam_fused_kernel(const float* __restrict__ mat,        // (80,20,20)
                        const float* __restrict__ val,        // (80,800)
                        const float* __restrict__ selfintact, // (40,40)
                        const float* __restrict__ neigintact, // (40,40)
                        float* __restrict__ out)              // (80,800)
{
    __shared__ __align__(16) float mF [PARAM * MST];  // F = S/2 - I
    __shared__ __align__(16) float mG [PARAM * MST];  // G = F^2
    __shared__ __align__(16) float mH [PARAM * MST];  // H = I + G + G^2
    __shared__ __align__(16) float mB [PARAM * MST];  // Bpre
    __shared__ __align__(16) float mNg[PARAM * MST];  // Ng
    __shared__ __align__(16) float mC [PARAM * MST];  // C = Bpre*Ng
    __shared__ __align__(16) float sx [NN];           // iterate
    __shared__ __align__(16) float sT [NN];           // T scratch
    __shared__ __align__(16) float sV [NN];           // v
    __shared__ __align__(16) float sM [GS * GS];      // M

    const int sys = blockIdx.x;
    const int t   = threadIdx.x;     // 0..799
    const int g   = t / PARAM;       // 0..19
    const int p   = t % PARAM;       // 0..39

    // ---- stage inputs ----
    {
        int i0 = t, i1 = t + NN;
        int r0 = i0 / PARAM, c0 = i0 % PARAM;
        int r1 = i1 / PARAM, c1 = i1 % PARAM;
        mF [r0 * MST + c0] = 0.5f * selfintact[i0] - (r0 == c0 ? 1.0f : 0.0f);
        mF [r1 * MST + c1] = 0.5f * selfintact[i1] - (r1 == c1 ? 1.0f : 0.0f);
        mNg[r0 * MST + c0] = neigintact[i0];
        mNg[r1 * MST + c1] = neigintact[i1];
        sV[t] = val[sys * NN + t];
        if (t < GS * GS) sM[t] = mat[sys * GS * GS + t];
    }
    __syncthreads();

    // ---- prep: 4 warp-cooperative GEMMs (10 warps each, R13 tiling) ----
    gemm40w<GM_PLAIN>(mG, mF, mF, t);   __syncthreads();  // G = F^2
    gemm40w<GM_H    >(mH, mG, mG, t);   __syncthreads();  // H = I + G + G^2
    gemm40w<GM_BF   >(mB, mF, mH, t);   __syncthreads();  // Bpre = 0.5(H - F*H)
    gemm40w<GM_PLAIN>(mC, mB, mNg, t);                    // C = Bpre*Ng
    // b = (I(x)Bpre) v for this element (mB ready above; all 800 threads).
    float b = rowdot40(&mB[p * MST], &sV[g * PARAM]);
    sx[t] = b;                        // x0 = b (sx untouched so far, no pre-barrier)
    __syncthreads();                  // mC stores + sx visible

    // ---- C[p,:] into registers ----
    float4 creg[10];
    #pragma unroll
    for (int i = 0; i < 10; ++i)
        creg[i] = *(const float4*)&mC[p * MST + 4 * i];

    const float*  Mrow = &sM[g * GS];
    const float4* xrow = (const float4*)&sx[g * PARAM];

    // ---- Richardson sweeps: x <- b - (M (x) C) x  (2 barriers/sweep) ----
    #pragma unroll 1
    for (int it = 0; it < NITER; ++it) {
        // Phase A: T[g,p] = sum_q C[p,q] x[g,q]
        float tv = 0.f;
        #pragma unroll
        for (int i = 0; i < 10; ++i) {
            float4 c  = creg[i];
            float4 x4 = xrow[i];        // broadcast within g-group
            tv = fmaf(c.x, x4.x, tv);
            tv = fmaf(c.y, x4.y, tv);
            tv = fmaf(c.z, x4.z, tv);
            tv = fmaf(c.w, x4.w, tv);
        }
        sT[t] = tv;
        __syncthreads();                // all phase-A sx reads + sT writes done

        // Phase B: x[g,p] = b - sum_g2 M[g,g2] T[g2,p]
        float acc = b;
        #pragma unroll
        for (int g2 = 0; g2 < GS; ++g2)
            acc = fmaf(-Mrow[g2], sT[g2 * PARAM + p], acc);  // M bcast, T conflict-free

        if (it == NITER - 1) {
            acc = fminf(fmaxf(acc, -1.0f), 1.0f);   // advrelu == clip
            out[sys * NN + t] = acc;
        } else {
            // safe: all phase-A sx reads completed before the barrier above
            sx[t] = acc;
            __syncthreads();
        }
    }
}

extern "C" void kernel_launch(void* const* d_in, const int* in_sizes, int n_in,
                              void* d_out, int out_size)
{
    const float* mat        = (const float*)d_in[0];
    const float* val        = (const float*)d_in[1];
    const float* selfintact = (const float*)d_in[2];
    const float* neigintact = (const float*)d_in[3];
    float* out = (float*)d_out;

    gliam_fused_kernel<<<NSYS, NN>>>(mat, val, selfintact, neigintact, out);
}